// round 1
// baseline (speedup 1.0000x reference)
#include <cuda_runtime.h>
#include <math.h>

// Problem constants
#define BB   2
#define SS   2048
#define HHID 2048
#define NH   16
#define NKV  4
#define HD   128
#define NTOK (BB*SS)       // 4096
#define QKV_LD 3072        // 16*128 q | 4*128 k | 4*128 v

// Scratch (device globals: allocation-free)
__device__ float g_qkv[(size_t)NTOK * QKV_LD];   // ~50 MB
__device__ float g_att[(size_t)NTOK * HHID];     // ~33 MB
__device__ float g_zeros[2048];                  // zero bias for final GEMM

// ======================= SGEMM (fp32, 128x128x16, 8x8/thread) =======================
#define GM_BM 128
#define GM_BN 128
#define GM_BK 16

__global__ __launch_bounds__(256, 2)
void sgemm_bias_kernel(const float* __restrict__ A, const float* __restrict__ B,
                       const float* __restrict__ bias, float* __restrict__ C,
                       int N, int K, int ldc)
{
    __shared__ float As[GM_BK][GM_BM + 4];
    __shared__ float Bs[GM_BK][GM_BN + 4];

    const int tid = threadIdx.x;
    const int tx = tid & 15, ty = tid >> 4;

    const float* Ab = A + (size_t)blockIdx.y * GM_BM * K;
    const float* Bb = B + (size_t)blockIdx.x * GM_BN;

    float acc[8][8];
#pragma unroll
    for (int i = 0; i < 8; i++)
#pragma unroll
        for (int j = 0; j < 8; j++) acc[i][j] = 0.0f;

    const int a_r  = tid >> 2;   // 0..63 (two rows: +0, +64)
    const int a_c4 = tid & 3;    // float4 index within 16-col row
    const int b_r  = tid >> 5;   // 0..7  (two rows: +0, +8)
    const int b_c4 = tid & 31;   // float4 index within 128-col row

    for (int k0 = 0; k0 < K; k0 += GM_BK) {
#pragma unroll
        for (int i = 0; i < 2; i++) {
            int r = a_r + i * 64;
            float4 v = *(const float4*)(Ab + (size_t)r * K + k0 + a_c4 * 4);
            As[a_c4 * 4 + 0][r] = v.x;
            As[a_c4 * 4 + 1][r] = v.y;
            As[a_c4 * 4 + 2][r] = v.z;
            As[a_c4 * 4 + 3][r] = v.w;
        }
#pragma unroll
        for (int i = 0; i < 2; i++) {
            int r = b_r + i * 8;
            *(float4*)&Bs[r][b_c4 * 4] = *(const float4*)(Bb + (size_t)(k0 + r) * N + b_c4 * 4);
        }
        __syncthreads();

#pragma unroll
        for (int k = 0; k < GM_BK; k++) {
            float af[8], bf[8];
            *(float4*)&af[0] = *(float4*)&As[k][ty * 4];
            *(float4*)&af[4] = *(float4*)&As[k][64 + ty * 4];
            *(float4*)&bf[0] = *(float4*)&Bs[k][tx * 4];
            *(float4*)&bf[4] = *(float4*)&Bs[k][64 + tx * 4];
#pragma unroll
            for (int i = 0; i < 8; i++)
#pragma unroll
                for (int j = 0; j < 8; j++)
                    acc[i][j] = fmaf(af[i], bf[j], acc[i][j]);
        }
        __syncthreads();
    }

#pragma unroll
    for (int ih = 0; ih < 2; ih++)
#pragma unroll
        for (int i = 0; i < 4; i++) {
            size_t r = (size_t)blockIdx.y * GM_BM + ih * 64 + ty * 4 + i;
#pragma unroll
            for (int jh = 0; jh < 2; jh++) {
                int cc = blockIdx.x * GM_BN + jh * 64 + tx * 4;
                float4 o;
                o.x = acc[ih * 4 + i][jh * 4 + 0] + bias[cc + 0];
                o.y = acc[ih * 4 + i][jh * 4 + 1] + bias[cc + 1];
                o.z = acc[ih * 4 + i][jh * 4 + 2] + bias[cc + 2];
                o.w = acc[ih * 4 + i][jh * 4 + 3] + bias[cc + 3];
                *(float4*)&C[r * ldc + cc] = o;
            }
        }
}

// ======================= continuous-time RoPE =======================
// Applies in-place to q (heads 0..15) and k (heads 16..19 => cols 2048..2559)
__global__ void rope_kernel(float* __restrict__ qkv, const float* __restrict__ timev,
                            const float* __restrict__ rope_w)
{
    __shared__ float cs[64], sn[64];
    const int token = blockIdx.x;
    const int tid = threadIdx.x;

    if (tid < 64) {
        float t = timev[token];
        // inv_freq = 10000^{-(2d/128)}, computed accurately; freq arg in fp32 like the ref
        float inv = (float)exp(-((double)(2 * tid) / 128.0) * log(10000.0));
        float f = t * inv * rope_w[tid];
        // double trig: robust to large args and to --use_fast_math
        cs[tid] = (float)cos((double)f);
        sn[tid] = (float)sin((double)f);
    }
    __syncthreads();

    float* base = qkv + (size_t)token * QKV_LD;
    for (int idx = tid; idx < 20 * 64; idx += blockDim.x) {
        int hh = idx >> 6;      // 0..19  (q heads 0..15, k heads 16..19 contiguous)
        int d  = idx & 63;
        float* p = base + hh * HD;
        float x1 = p[d], x2 = p[d + 64];
        p[d]      = x1 * cs[d] - x2 * sn[d];
        p[d + 64] = x2 * cs[d] + x1 * sn[d];
    }
}

// ======================= causal flash attention (fp32) =======================
// BM=BN=64, D=128, 256 threads, online softmax. One block per (q-tile, b, h).
#define AT_SMEM_FLOATS (3 * 64 * 132 + 64 * 68 + 3 * 64)
#define AT_SMEM_BYTES  (AT_SMEM_FLOATS * 4)

__global__ __launch_bounds__(256, 1)
void attn_kernel(const float* __restrict__ qkv, float* __restrict__ att)
{
    extern __shared__ float sm[];
    float (*q_s)[132] = (float (*)[132])(sm);
    float (*k_s)[132] = (float (*)[132])(sm + 64 * 132);
    float (*v_s)[132] = (float (*)[132])(sm + 2 * 64 * 132);
    float (*s_s)[68]  = (float (*)[68]) (sm + 3 * 64 * 132);
    float* m_s  = sm + 3 * 64 * 132 + 64 * 68;
    float* l_s  = m_s + 64;
    float* al_s = l_s + 64;

    const int qt = blockIdx.x;          // query tile (64 rows)
    const int bh = blockIdx.y;          // b*16 + h
    const int b = bh >> 4, h = bh & 15, g = h >> 2;   // GQA: head h -> kv head h/4
    const int tid  = threadIdx.x;
    const int tx = tid & 15, ty = tid >> 4;
    const int warp = tid >> 5, lane = tid & 31;
    const float scale = 0.088388347648318447f;   // 1/sqrt(128)

    const float* qb = qkv + (size_t)b * SS * QKV_LD + h * HD;
    const float* kb = qkv + (size_t)b * SS * QKV_LD + 2048 + g * HD;
    const float* vb = qkv + (size_t)b * SS * QKV_LD + 2560 + g * HD;

    // Load Q tile (64 x 128)
    {
        int c4 = tid & 31, r0 = tid >> 5;
#pragma unroll
        for (int i = 0; i < 8; i++) {
            int r = r0 + i * 8;
            *(float4*)&q_s[r][c4 * 4] =
                *(const float4*)(qb + (size_t)(qt * 64 + r) * QKV_LD + c4 * 4);
        }
    }
    if (tid < 64) { m_s[tid] = -1e30f; l_s[tid] = 0.0f; }

    float o[4][8];
#pragma unroll
    for (int i = 0; i < 4; i++)
#pragma unroll
        for (int j = 0; j < 8; j++) o[i][j] = 0.0f;

    for (int jt = 0; jt <= qt; jt++) {
        // Load K,V tiles
        {
            int c4 = tid & 31, r0 = tid >> 5;
#pragma unroll
            for (int i = 0; i < 8; i++) {
                int r = r0 + i * 8;
                size_t off = (size_t)(jt * 64 + r) * QKV_LD + c4 * 4;
                *(float4*)&k_s[r][c4 * 4] = *(const float4*)(kb + off);
                *(float4*)&v_s[r][c4 * 4] = *(const float4*)(vb + off);
            }
        }
        __syncthreads();

        // S = scale * Q K^T  (rows ty+16i, cols tx+16j to keep LDS <=2-way)
        float sacc[4][4];
#pragma unroll
        for (int i = 0; i < 4; i++)
#pragma unroll
            for (int j = 0; j < 4; j++) sacc[i][j] = 0.0f;

#pragma unroll
        for (int k4 = 0; k4 < 32; k4++) {
            float4 qv[4], kv[4];
#pragma unroll
            for (int i = 0; i < 4; i++) qv[i] = *(float4*)&q_s[ty + 16 * i][k4 * 4];
#pragma unroll
            for (int j = 0; j < 4; j++) kv[j] = *(float4*)&k_s[tx + 16 * j][k4 * 4];
#pragma unroll
            for (int i = 0; i < 4; i++)
#pragma unroll
                for (int j = 0; j < 4; j++) {
                    sacc[i][j] = fmaf(qv[i].x, kv[j].x, sacc[i][j]);
                    sacc[i][j] = fmaf(qv[i].y, kv[j].y, sacc[i][j]);
                    sacc[i][j] = fmaf(qv[i].z, kv[j].z, sacc[i][j]);
                    sacc[i][j] = fmaf(qv[i].w, kv[j].w, sacc[i][j]);
                }
        }
#pragma unroll
        for (int i = 0; i < 4; i++)
#pragma unroll
            for (int j = 0; j < 4; j++) {
                int r = ty + 16 * i, c = tx + 16 * j;
                bool mask = (jt * 64 + c) > (qt * 64 + r);
                s_s[r][c] = mask ? -1e30f : sacc[i][j] * scale;
            }
        __syncthreads();

        // Online softmax: warp w processes rows w*8..w*8+7
#pragma unroll
        for (int rr = 0; rr < 8; rr++) {
            int r = warp * 8 + rr;
            float s0 = s_s[r][lane], s1 = s_s[r][lane + 32];
            float mt = fmaxf(s0, s1);
#pragma unroll
            for (int off = 16; off > 0; off >>= 1)
                mt = fmaxf(mt, __shfl_xor_sync(0xffffffffu, mt, off));
            float m_old = m_s[r];
            float m_new = fmaxf(m_old, mt);
            float p0 = __expf(s0 - m_new);
            float p1 = __expf(s1 - m_new);
            float ps = p0 + p1;
#pragma unroll
            for (int off = 16; off > 0; off >>= 1)
                ps += __shfl_xor_sync(0xffffffffu, ps, off);
            s_s[r][lane] = p0;
            s_s[r][lane + 32] = p1;
            if (lane == 0) {
                float alpha = __expf(m_old - m_new);
                m_s[r]  = m_new;
                l_s[r]  = l_s[r] * alpha + ps;
                al_s[r] = alpha;
            }
        }
        __syncthreads();

        // Rescale O, then O += P V
#pragma unroll
        for (int i = 0; i < 4; i++) {
            float a = al_s[ty + 16 * i];
#pragma unroll
            for (int j = 0; j < 8; j++) o[i][j] *= a;
        }
#pragma unroll 8
        for (int c = 0; c < 64; c++) {
            float4 v0 = *(float4*)&v_s[c][tx * 4];
            float4 v1 = *(float4*)&v_s[c][64 + tx * 4];
#pragma unroll
            for (int i = 0; i < 4; i++) {
                float p = s_s[ty + 16 * i][c];
                o[i][0] = fmaf(p, v0.x, o[i][0]);
                o[i][1] = fmaf(p, v0.y, o[i][1]);
                o[i][2] = fmaf(p, v0.z, o[i][2]);
                o[i][3] = fmaf(p, v0.w, o[i][3]);
                o[i][4] = fmaf(p, v1.x, o[i][4]);
                o[i][5] = fmaf(p, v1.y, o[i][5]);
                o[i][6] = fmaf(p, v1.z, o[i][6]);
                o[i][7] = fmaf(p, v1.w, o[i][7]);
            }
        }
        __syncthreads();
    }

    // Normalize and write to att[(b,s), h*128 + d]
#pragma unroll
    for (int i = 0; i < 4; i++) {
        int r = ty + 16 * i;
        float inv_l = 1.0f / l_s[r];
        size_t row = (size_t)(b * SS + qt * 64 + r);
        float4 o0, o1;
        o0.x = o[i][0] * inv_l; o0.y = o[i][1] * inv_l;
        o0.z = o[i][2] * inv_l; o0.w = o[i][3] * inv_l;
        o1.x = o[i][4] * inv_l; o1.y = o[i][5] * inv_l;
        o1.z = o[i][6] * inv_l; o1.w = o[i][7] * inv_l;
        *(float4*)&att[row * HHID + h * HD + tx * 4]      = o0;
        *(float4*)&att[row * HHID + h * HD + 64 + tx * 4] = o1;
    }
}

// ======================= launch =======================
extern "C" void kernel_launch(void* const* d_in, const int* in_sizes, int n_in,
                              void* d_out, int out_size)
{
    const float* hidden = (const float*)d_in[0];
    const float* timev  = (const float*)d_in[1];
    const float* wq = (const float*)d_in[2];
    const float* bq = (const float*)d_in[3];
    const float* wk = (const float*)d_in[4];
    const float* bk = (const float*)d_in[5];
    const float* wv = (const float*)d_in[6];
    const float* bv = (const float*)d_in[7];
    const float* wo = (const float*)d_in[8];
    const float* rw = (const float*)d_in[9];
    float* out = (float*)d_out;

    float *qkv, *att, *zb;
    cudaGetSymbolAddress((void**)&qkv, g_qkv);
    cudaGetSymbolAddress((void**)&att, g_att);
    cudaGetSymbolAddress((void**)&zb,  g_zeros);

    dim3 blk(256);
    // QKV projections -> [4096, 3072] scratch (q | k | v)
    sgemm_bias_kernel<<<dim3(16, 32), blk>>>(hidden, wq, bq, qkv,        2048, 2048, QKV_LD);
    sgemm_bias_kernel<<<dim3(4, 32),  blk>>>(hidden, wk, bk, qkv + 2048,  512, 2048, QKV_LD);
    sgemm_bias_kernel<<<dim3(4, 32),  blk>>>(hidden, wv, bv, qkv + 2560,  512, 2048, QKV_LD);

    // Continuous-time RoPE on q and k (in place)
    rope_kernel<<<NTOK, 256>>>(qkv, timev, rw);

    // Causal GQA flash attention -> [4096, 2048] (b,s, h*hd)
    cudaFuncSetAttribute(attn_kernel, cudaFuncAttributeMaxDynamicSharedMemorySize, AT_SMEM_BYTES);
    attn_kernel<<<dim3(SS / 64, BB * NH), blk, AT_SMEM_BYTES>>>(qkv, att);

    // Output projection -> d_out [4096, 2048]
    sgemm_bias_kernel<<<dim3(16, 32), blk>>>(att, wo, zb, out, 2048, 2048, 2048);
}

// round 10
// speedup vs baseline: 2.0811x; 2.0811x over previous
#include <cuda_runtime.h>
#include <math.h>
#include <stdint.h>

// Problem constants
#define BB   2
#define SS   2048
#define HHID 2048
#define NH   16
#define NKV  4
#define HD   128
#define NTOK (BB*SS)       // 4096
#define QKV_LD 3072        // 16*128 q | 4*128 k | 4*128 v

// Scratch (device globals: allocation-free)
__device__ float g_qkv[(size_t)NTOK * QKV_LD];   // ~50 MB
__device__ float g_att[(size_t)NTOK * HHID];     // ~33 MB
__device__ float g_zeros[2048];                  // zero bias for final GEMM

__device__ __forceinline__ uint32_t f2tf32(float x) {
    uint32_t y;
    asm("cvt.rna.tf32.f32 %0, %1;" : "=r"(y) : "f"(x));
    return y;
}

__device__ __forceinline__ void mma_tf32(float* c, uint32_t a0, uint32_t a1,
                                         uint32_t a2, uint32_t a3,
                                         uint32_t b0, uint32_t b1)
{
    asm volatile(
        "mma.sync.aligned.m16n8k8.row.col.f32.tf32.tf32.f32 "
        "{%0,%1,%2,%3}, {%4,%5,%6,%7}, {%8,%9}, {%0,%1,%2,%3};"
        : "+f"(c[0]), "+f"(c[1]), "+f"(c[2]), "+f"(c[3])
        : "r"(a0), "r"(a1), "r"(a2), "r"(a3), "r"(b0), "r"(b1));
}

// ======================= tf32 tensor-core GEMM =======================
// C[M,N] = A[M,K] @ B[K,N] + bias, tile 128x128x32, mma.m16n8k8.tf32
__global__ __launch_bounds__(256, 2)
void gemm_tf32_kernel(const float* __restrict__ A, const float* __restrict__ B,
                      const float* __restrict__ bias, float* __restrict__ C,
                      int N, int K, int ldc)
{
    __shared__ float As[128][36];
    __shared__ float Bs[32][132];

    const int tid  = threadIdx.x;
    const int warp = tid >> 5, lane = tid & 31;
    const int wm = warp >> 1;
    const int wn = warp & 1;
    const int g  = lane >> 2;
    const int t  = lane & 3;

    const float* Ab = A + (size_t)blockIdx.y * 128 * K;
    const float* Bb = B + (size_t)blockIdx.x * 128;

    float acc[2][8][4];
#pragma unroll
    for (int i = 0; i < 2; i++)
#pragma unroll
        for (int j = 0; j < 8; j++)
#pragma unroll
            for (int c = 0; c < 4; c++) acc[i][j][c] = 0.0f;

    const int a_row = tid >> 3;
    const int a_c4  = tid & 7;
    const int b_row = tid >> 5;
    const int b_c4  = tid & 31;

    for (int k0 = 0; k0 < K; k0 += 32) {
#pragma unroll
        for (int p = 0; p < 4; p++) {
            int r = p * 32 + a_row;
            float4 v = *(const float4*)(Ab + (size_t)r * K + k0 + a_c4 * 4);
            float4 w;
            w.x = __uint_as_float(f2tf32(v.x));
            w.y = __uint_as_float(f2tf32(v.y));
            w.z = __uint_as_float(f2tf32(v.z));
            w.w = __uint_as_float(f2tf32(v.w));
            *(float4*)&As[r][a_c4 * 4] = w;
        }
#pragma unroll
        for (int p = 0; p < 4; p++) {
            int r = p * 8 + b_row;
            float4 v = *(const float4*)(Bb + (size_t)(k0 + r) * N + b_c4 * 4);
            float4 w;
            w.x = __uint_as_float(f2tf32(v.x));
            w.y = __uint_as_float(f2tf32(v.y));
            w.z = __uint_as_float(f2tf32(v.z));
            w.w = __uint_as_float(f2tf32(v.w));
            *(float4*)&Bs[r][b_c4 * 4] = w;
        }
        __syncthreads();

#pragma unroll
        for (int kk = 0; kk < 4; kk++) {
            const int kb = kk * 8;
            uint32_t af[2][4];
#pragma unroll
            for (int mt = 0; mt < 2; mt++) {
                int rb = wm * 32 + mt * 16;
                af[mt][0] = __float_as_uint(As[rb + g    ][kb + t    ]);
                af[mt][1] = __float_as_uint(As[rb + g + 8][kb + t    ]);
                af[mt][2] = __float_as_uint(As[rb + g    ][kb + t + 4]);
                af[mt][3] = __float_as_uint(As[rb + g + 8][kb + t + 4]);
            }
            uint32_t bf[8][2];
#pragma unroll
            for (int nt = 0; nt < 8; nt++) {
                int cn = wn * 64 + nt * 8 + g;
                bf[nt][0] = __float_as_uint(Bs[kb + t    ][cn]);
                bf[nt][1] = __float_as_uint(Bs[kb + t + 4][cn]);
            }
#pragma unroll
            for (int mt = 0; mt < 2; mt++)
#pragma unroll
                for (int nt = 0; nt < 8; nt++)
                    mma_tf32(acc[mt][nt], af[mt][0], af[mt][1], af[mt][2], af[mt][3],
                             bf[nt][0], bf[nt][1]);
        }
        __syncthreads();
    }

#pragma unroll
    for (int mt = 0; mt < 2; mt++) {
        size_t r0 = (size_t)blockIdx.y * 128 + wm * 32 + mt * 16 + g;
#pragma unroll
        for (int nt = 0; nt < 8; nt++) {
            int col = blockIdx.x * 128 + wn * 64 + nt * 8 + 2 * t;
            float2 bv = *(const float2*)&bias[col];
            float2 o0, o1;
            o0.x = acc[mt][nt][0] + bv.x;  o0.y = acc[mt][nt][1] + bv.y;
            o1.x = acc[mt][nt][2] + bv.x;  o1.y = acc[mt][nt][3] + bv.y;
            *(float2*)&C[r0 * ldc + col]       = o0;
            *(float2*)&C[(r0 + 8) * ldc + col] = o1;
        }
    }
}

// ======================= continuous-time RoPE =======================
__global__ void rope_kernel(float* __restrict__ qkv, const float* __restrict__ timev,
                            const float* __restrict__ rope_w)
{
    __shared__ float cs[64], sn[64];
    const int token = blockIdx.x;
    const int tid = threadIdx.x;

    if (tid < 64) {
        float t = timev[token];
        float inv = (float)exp(-((double)(2 * tid) / 128.0) * log(10000.0));
        float f = t * inv * rope_w[tid];
        cs[tid] = (float)cos((double)f);
        sn[tid] = (float)sin((double)f);
    }
    __syncthreads();

    float* base = qkv + (size_t)token * QKV_LD;
    for (int idx = tid; idx < 20 * 64; idx += blockDim.x) {
        int hh = idx >> 6;
        int d  = idx & 63;
        float* p = base + hh * HD;
        float x1 = p[d], x2 = p[d + 64];
        p[d]      = x1 * cs[d] - x2 * sn[d];
        p[d + 64] = x2 * cs[d] + x1 * sn[d];
    }
}

// ======================= causal flash attention (tf32 MMA) =======================
// BM=BN=64, D=128, 256 threads. QK^T and PV on m16n8k8.tf32; S round-trips
// through smem so the validated smem softmax is reused unchanged.
#define AT_SMEM_FLOATS (3 * 64 * 132 + 64 * 68 + 3 * 64)
#define AT_SMEM_BYTES  (AT_SMEM_FLOATS * 4)

__global__ __launch_bounds__(256, 1)
void attn_kernel(const float* __restrict__ qkv, float* __restrict__ att)
{
    extern __shared__ float sm[];
    float (*q_s)[132] = (float (*)[132])(sm);
    float (*k_s)[132] = (float (*)[132])(sm + 64 * 132);
    float (*v_s)[132] = (float (*)[132])(sm + 2 * 64 * 132);
    float (*s_s)[68]  = (float (*)[68]) (sm + 3 * 64 * 132);
    float* m_s  = sm + 3 * 64 * 132 + 64 * 68;
    float* l_s  = m_s + 64;
    float* al_s = l_s + 64;

    const int qt = blockIdx.x;
    const int bh = blockIdx.y;
    const int b = bh >> 4, h = bh & 15, gq = h >> 2;
    const int tid  = threadIdx.x;
    const int warp = tid >> 5, lane = tid & 31;
    const int wm = warp >> 1;        // 0..3: 16 q-rows each
    const int wn = warp & 1;         // 0..1
    const int g  = lane >> 2;        // 0..7
    const int t  = lane & 3;         // 0..3
    const float scale = 0.088388347648318447f;   // 1/sqrt(128)

    const float* qb = qkv + (size_t)b * SS * QKV_LD + h * HD;
    const float* kb = qkv + (size_t)b * SS * QKV_LD + 2048 + gq * HD;
    const float* vb = qkv + (size_t)b * SS * QKV_LD + 2560 + gq * HD;

    // Load Q tile (64 x 128), tf32-converted
    {
        int c4 = tid & 31, r0 = tid >> 5;
#pragma unroll
        for (int i = 0; i < 8; i++) {
            int r = r0 + i * 8;
            float4 v = *(const float4*)(qb + (size_t)(qt * 64 + r) * QKV_LD + c4 * 4);
            float4 w;
            w.x = __uint_as_float(f2tf32(v.x));
            w.y = __uint_as_float(f2tf32(v.y));
            w.z = __uint_as_float(f2tf32(v.z));
            w.w = __uint_as_float(f2tf32(v.w));
            *(float4*)&q_s[r][c4 * 4] = w;
        }
    }
    if (tid < 64) { m_s[tid] = -1e30f; l_s[tid] = 0.0f; }

    // O accumulators: warp (wm,wn) owns rows wm*16+{g,g+8}, d-cols wn*64 + 8 tiles
    float oacc[8][4];
#pragma unroll
    for (int i = 0; i < 8; i++)
#pragma unroll
        for (int c = 0; c < 4; c++) oacc[i][c] = 0.0f;

    for (int jt = 0; jt <= qt; jt++) {
        // Load K,V tiles (tf32)
        {
            int c4 = tid & 31, r0 = tid >> 5;
#pragma unroll
            for (int i = 0; i < 8; i++) {
                int r = r0 + i * 8;
                size_t off = (size_t)(jt * 64 + r) * QKV_LD + c4 * 4;
                float4 kv4 = *(const float4*)(kb + off);
                float4 vv4 = *(const float4*)(vb + off);
                float4 wk4, wv4;
                wk4.x = __uint_as_float(f2tf32(kv4.x));
                wk4.y = __uint_as_float(f2tf32(kv4.y));
                wk4.z = __uint_as_float(f2tf32(kv4.z));
                wk4.w = __uint_as_float(f2tf32(kv4.w));
                wv4.x = __uint_as_float(f2tf32(vv4.x));
                wv4.y = __uint_as_float(f2tf32(vv4.y));
                wv4.z = __uint_as_float(f2tf32(vv4.z));
                wv4.w = __uint_as_float(f2tf32(vv4.w));
                *(float4*)&k_s[r][c4 * 4] = wk4;
                *(float4*)&v_s[r][c4 * 4] = wv4;
            }
        }
        __syncthreads();

        // S = Q K^T via MMA. Warp: m-tile rows wm*16, n-tiles wn*32 + 4 tiles.
        float sacc[4][4];
#pragma unroll
        for (int j = 0; j < 4; j++)
#pragma unroll
            for (int c = 0; c < 4; c++) sacc[j][c] = 0.0f;

#pragma unroll
        for (int kk = 0; kk < 16; kk++) {
            const int kb8 = kk * 8;
            uint32_t a0 = __float_as_uint(q_s[wm * 16 + g    ][kb8 + t    ]);
            uint32_t a1 = __float_as_uint(q_s[wm * 16 + g + 8][kb8 + t    ]);
            uint32_t a2 = __float_as_uint(q_s[wm * 16 + g    ][kb8 + t + 4]);
            uint32_t a3 = __float_as_uint(q_s[wm * 16 + g + 8][kb8 + t + 4]);
#pragma unroll
            for (int nt = 0; nt < 4; nt++) {
                int kr = wn * 32 + nt * 8 + g;   // K row (= S col group)
                uint32_t b0 = __float_as_uint(k_s[kr][kb8 + t    ]);
                uint32_t b1 = __float_as_uint(k_s[kr][kb8 + t + 4]);
                mma_tf32(sacc[nt], a0, a1, a2, a3, b0, b1);
            }
        }

        // Scale + causal mask + store fragments to s_s
        {
            int r0 = wm * 16 + g, r1 = r0 + 8;
            int gr0 = qt * 64 + r0, gr1 = qt * 64 + r1;
#pragma unroll
            for (int nt = 0; nt < 4; nt++) {
                int c0 = wn * 32 + nt * 8 + 2 * t;
                int gc0 = jt * 64 + c0;
                s_s[r0][c0]     = (gc0     > gr0) ? -1e30f : sacc[nt][0] * scale;
                s_s[r0][c0 + 1] = (gc0 + 1 > gr0) ? -1e30f : sacc[nt][1] * scale;
                s_s[r1][c0]     = (gc0     > gr1) ? -1e30f : sacc[nt][2] * scale;
                s_s[r1][c0 + 1] = (gc0 + 1 > gr1) ? -1e30f : sacc[nt][3] * scale;
            }
        }
        __syncthreads();

        // Online softmax on s_s (validated path; p stored tf32-converted)
#pragma unroll
        for (int rr = 0; rr < 8; rr++) {
            int r = warp * 8 + rr;
            float s0 = s_s[r][lane], s1 = s_s[r][lane + 32];
            float mt = fmaxf(s0, s1);
#pragma unroll
            for (int off = 16; off > 0; off >>= 1)
                mt = fmaxf(mt, __shfl_xor_sync(0xffffffffu, mt, off));
            float m_old = m_s[r];
            float m_new = fmaxf(m_old, mt);
            float p0 = __expf(s0 - m_new);
            float p1 = __expf(s1 - m_new);
            float ps = p0 + p1;
#pragma unroll
            for (int off = 16; off > 0; off >>= 1)
                ps += __shfl_xor_sync(0xffffffffu, ps, off);
            s_s[r][lane]      = __uint_as_float(f2tf32(p0));
            s_s[r][lane + 32] = __uint_as_float(f2tf32(p1));
            if (lane == 0) {
                float alpha = __expf(m_old - m_new);
                m_s[r]  = m_new;
                l_s[r]  = l_s[r] * alpha + ps;
                al_s[r] = alpha;
            }
        }
        __syncthreads();

        // Rescale O by alpha, then O += P V via MMA
        {
            float a_lo = al_s[wm * 16 + g];
            float a_hi = al_s[wm * 16 + g + 8];
#pragma unroll
            for (int nt = 0; nt < 8; nt++) {
                oacc[nt][0] *= a_lo;  oacc[nt][1] *= a_lo;
                oacc[nt][2] *= a_hi;  oacc[nt][3] *= a_hi;
            }
        }
#pragma unroll
        for (int kk = 0; kk < 8; kk++) {
            const int kb8 = kk * 8;
            uint32_t a0 = __float_as_uint(s_s[wm * 16 + g    ][kb8 + t    ]);
            uint32_t a1 = __float_as_uint(s_s[wm * 16 + g + 8][kb8 + t    ]);
            uint32_t a2 = __float_as_uint(s_s[wm * 16 + g    ][kb8 + t + 4]);
            uint32_t a3 = __float_as_uint(s_s[wm * 16 + g + 8][kb8 + t + 4]);
#pragma unroll
            for (int nt = 0; nt < 8; nt++) {
                int cn = wn * 64 + nt * 8 + g;
                uint32_t b0 = __float_as_uint(v_s[kb8 + t    ][cn]);
                uint32_t b1 = __float_as_uint(v_s[kb8 + t + 4][cn]);
                mma_tf32(oacc[nt], a0, a1, a2, a3, b0, b1);
            }
        }
        __syncthreads();
    }

    // Normalize and write O: rows wm*16+{g,g+8}, cols wn*64 + nt*8 + 2t
    {
        int r0 = wm * 16 + g, r1 = r0 + 8;
        float il0 = 1.0f / l_s[r0];
        float il1 = 1.0f / l_s[r1];
        size_t row0 = (size_t)(b * SS + qt * 64 + r0);
        size_t row1 = (size_t)(b * SS + qt * 64 + r1);
#pragma unroll
        for (int nt = 0; nt < 8; nt++) {
            int col = h * HD + wn * 64 + nt * 8 + 2 * t;
            float2 o0, o1;
            o0.x = oacc[nt][0] * il0;  o0.y = oacc[nt][1] * il0;
            o1.x = oacc[nt][2] * il1;  o1.y = oacc[nt][3] * il1;
            *(float2*)&att[row0 * HHID + col] = o0;
            *(float2*)&att[row1 * HHID + col] = o1;
        }
    }
}

// ======================= launch =======================
extern "C" void kernel_launch(void* const* d_in, const int* in_sizes, int n_in,
                              void* d_out, int out_size)
{
    const float* hidden = (const float*)d_in[0];
    const float* timev  = (const float*)d_in[1];
    const float* wq = (const float*)d_in[2];
    const float* bq = (const float*)d_in[3];
    const float* wk = (const float*)d_in[4];
    const float* bk = (const float*)d_in[5];
    const float* wv = (const float*)d_in[6];
    const float* bv = (const float*)d_in[7];
    const float* wo = (const float*)d_in[8];
    const float* rw = (const float*)d_in[9];
    float* out = (float*)d_out;

    float *qkv, *att, *zb;
    cudaGetSymbolAddress((void**)&qkv, g_qkv);
    cudaGetSymbolAddress((void**)&att, g_att);
    cudaGetSymbolAddress((void**)&zb,  g_zeros);

    dim3 blk(256);
    // QKV projections -> [4096, 3072] scratch (q | k | v), tf32 tensor cores
    gemm_tf32_kernel<<<dim3(16, 32), blk>>>(hidden, wq, bq, qkv,        2048, 2048, QKV_LD);
    gemm_tf32_kernel<<<dim3(4, 32),  blk>>>(hidden, wk, bk, qkv + 2048,  512, 2048, QKV_LD);
    gemm_tf32_kernel<<<dim3(4, 32),  blk>>>(hidden, wv, bv, qkv + 2560,  512, 2048, QKV_LD);

    // Continuous-time RoPE on q and k (in place)
    rope_kernel<<<NTOK, 256>>>(qkv, timev, rw);

    // Causal GQA flash attention (tf32 MMA) -> [4096, 2048]
    cudaFuncSetAttribute(attn_kernel, cudaFuncAttributeMaxDynamicSharedMemorySize, AT_SMEM_BYTES);
    attn_kernel<<<dim3(SS / 64, BB * NH), blk, AT_SMEM_BYTES>>>(qkv, att);

    // Output projection -> d_out [4096, 2048], tf32 tensor cores
    gemm_tf32_kernel<<<dim3(16, 32), blk>>>(att, wo, zb, out, 2048, 2048, 2048);
}

// round 11
// speedup vs baseline: 2.2319x; 1.0725x over previous
#include <cuda_runtime.h>
#include <math.h>
#include <stdint.h>

// Problem constants
#define BB   2
#define SS   2048
#define HHID 2048
#define NH   16
#define NKV  4
#define HD   128
#define NTOK (BB*SS)       // 4096
#define QKV_LD 3072        // 16*128 q | 4*128 k | 4*128 v

// Scratch (device globals: allocation-free)
__device__ float g_qkv[(size_t)NTOK * QKV_LD];   // ~50 MB
__device__ float g_att[(size_t)NTOK * HHID];     // ~33 MB
__device__ float g_zeros[2048];                  // zero bias for final GEMM

__device__ __forceinline__ uint32_t f2tf32(float x) {
    uint32_t y;
    asm("cvt.rna.tf32.f32 %0, %1;" : "=r"(y) : "f"(x));
    return y;
}

__device__ __forceinline__ void mma_tf32(float* c, uint32_t a0, uint32_t a1,
                                         uint32_t a2, uint32_t a3,
                                         uint32_t b0, uint32_t b1)
{
    asm volatile(
        "mma.sync.aligned.m16n8k8.row.col.f32.tf32.tf32.f32 "
        "{%0,%1,%2,%3}, {%4,%5,%6,%7}, {%8,%9}, {%0,%1,%2,%3};"
        : "+f"(c[0]), "+f"(c[1]), "+f"(c[2]), "+f"(c[3])
        : "r"(a0), "r"(a1), "r"(a2), "r"(a3), "r"(b0), "r"(b1));
}

__device__ __forceinline__ void cp_async16(uint32_t dst_smem, const void* src) {
    asm volatile("cp.async.cg.shared.global [%0], [%1], 16;"
                 :: "r"(dst_smem), "l"(src));
}

// ======================= tf32 tensor-core GEMM, cp.async 2-stage =======================
// C[M,N] = A[M,K] @ B[K,N] + bias, tile 128x128x32, mma.m16n8k8.tf32
// Raw fp32 staged via cp.async; rna-tf32 conversion at fragment load (numerics
// identical to convert-at-fill).
#define GM_AS_FLOATS (128 * 36)
#define GM_BS_FLOATS (32 * 132)
#define GM_SMEM_FLOATS (2 * (GM_AS_FLOATS + GM_BS_FLOATS))
#define GM_SMEM_BYTES (GM_SMEM_FLOATS * 4)   // 70656

__global__ __launch_bounds__(256, 2)
void gemm_tf32_kernel(const float* __restrict__ A, const float* __restrict__ B,
                      const float* __restrict__ bias, float* __restrict__ C,
                      int N, int K, int ldc)
{
    extern __shared__ float gsm[];
    // Stage s: As = gsm + s*GM_AS_FLOATS               [128][36]
    //          Bs = gsm + 2*GM_AS_FLOATS + s*GM_BS_FLOATS  [32][132]

    const int tid  = threadIdx.x;
    const int warp = tid >> 5, lane = tid & 31;
    const int wm = warp >> 1;
    const int wn = warp & 1;
    const int g  = lane >> 2;
    const int t  = lane & 3;

    const float* Ab = A + (size_t)blockIdx.y * 128 * K;
    const float* Bb = B + (size_t)blockIdx.x * 128;

    float acc[2][8][4];
#pragma unroll
    for (int i = 0; i < 2; i++)
#pragma unroll
        for (int j = 0; j < 8; j++)
#pragma unroll
            for (int c = 0; c < 4; c++) acc[i][j][c] = 0.0f;

    const int a_row = tid >> 3;   // 0..31, 4 passes of 32 rows
    const int a_c4  = tid & 7;    // 16B chunk within 32-col row
    const int b_row = tid >> 5;   // 0..7,  4 passes of 8 rows
    const int b_c4  = tid & 31;   // 16B chunk within 128-col row

    const uint32_t smbase = (uint32_t)__cvta_generic_to_shared(gsm);

    auto issue = [&](int stage, int k0) {
        uint32_t as_base = smbase + (uint32_t)(stage * GM_AS_FLOATS) * 4u;
        uint32_t bs_base = smbase + (uint32_t)(2 * GM_AS_FLOATS + stage * GM_BS_FLOATS) * 4u;
#pragma unroll
        for (int p = 0; p < 4; p++) {
            int r = p * 32 + a_row;
            cp_async16(as_base + (uint32_t)(r * 36 + a_c4 * 4) * 4u,
                       Ab + (size_t)r * K + k0 + a_c4 * 4);
        }
#pragma unroll
        for (int p = 0; p < 4; p++) {
            int r = p * 8 + b_row;
            cp_async16(bs_base + (uint32_t)(r * 132 + b_c4 * 4) * 4u,
                       Bb + (size_t)(k0 + r) * N + b_c4 * 4);
        }
        asm volatile("cp.async.commit_group;");
    };

    const int ntiles = K / 32;
    issue(0, 0);
    int stage = 0;

    for (int i = 0; i < ntiles; i++) {
        asm volatile("cp.async.wait_group 0;");
        __syncthreads();   // stage data visible to all; prior compute done before next issue
        if (i + 1 < ntiles) issue(stage ^ 1, (i + 1) * 32);

        const float* As = gsm + stage * GM_AS_FLOATS;
        const float* Bs = gsm + 2 * GM_AS_FLOATS + stage * GM_BS_FLOATS;

#pragma unroll
        for (int kk = 0; kk < 4; kk++) {
            const int kb = kk * 8;
            uint32_t af[2][4];
#pragma unroll
            for (int mt = 0; mt < 2; mt++) {
                int rb = wm * 32 + mt * 16;
                af[mt][0] = f2tf32(As[(rb + g    ) * 36 + kb + t    ]);
                af[mt][1] = f2tf32(As[(rb + g + 8) * 36 + kb + t    ]);
                af[mt][2] = f2tf32(As[(rb + g    ) * 36 + kb + t + 4]);
                af[mt][3] = f2tf32(As[(rb + g + 8) * 36 + kb + t + 4]);
            }
            uint32_t bf[8][2];
#pragma unroll
            for (int nt = 0; nt < 8; nt++) {
                int cn = wn * 64 + nt * 8 + g;
                bf[nt][0] = f2tf32(Bs[(kb + t    ) * 132 + cn]);
                bf[nt][1] = f2tf32(Bs[(kb + t + 4) * 132 + cn]);
            }
#pragma unroll
            for (int mt = 0; mt < 2; mt++)
#pragma unroll
                for (int nt = 0; nt < 8; nt++)
                    mma_tf32(acc[mt][nt], af[mt][0], af[mt][1], af[mt][2], af[mt][3],
                             bf[nt][0], bf[nt][1]);
        }
        stage ^= 1;
    }

#pragma unroll
    for (int mt = 0; mt < 2; mt++) {
        size_t r0 = (size_t)blockIdx.y * 128 + wm * 32 + mt * 16 + g;
#pragma unroll
        for (int nt = 0; nt < 8; nt++) {
            int col = blockIdx.x * 128 + wn * 64 + nt * 8 + 2 * t;
            float2 bv = *(const float2*)&bias[col];
            float2 o0, o1;
            o0.x = acc[mt][nt][0] + bv.x;  o0.y = acc[mt][nt][1] + bv.y;
            o1.x = acc[mt][nt][2] + bv.x;  o1.y = acc[mt][nt][3] + bv.y;
            *(float2*)&C[r0 * ldc + col]       = o0;
            *(float2*)&C[(r0 + 8) * ldc + col] = o1;
        }
    }
}

// ======================= continuous-time RoPE =======================
__global__ void rope_kernel(float* __restrict__ qkv, const float* __restrict__ timev,
                            const float* __restrict__ rope_w)
{
    __shared__ float cs[64], sn[64];
    const int token = blockIdx.x;
    const int tid = threadIdx.x;

    if (tid < 64) {
        float t = timev[token];
        float inv = (float)exp(-((double)(2 * tid) / 128.0) * log(10000.0));
        float f = t * inv * rope_w[tid];
        cs[tid] = (float)cos((double)f);
        sn[tid] = (float)sin((double)f);
    }
    __syncthreads();

    float* base = qkv + (size_t)token * QKV_LD;
    for (int idx = tid; idx < 20 * 64; idx += blockDim.x) {
        int hh = idx >> 6;
        int d  = idx & 63;
        float* p = base + hh * HD;
        float x1 = p[d], x2 = p[d + 64];
        p[d]      = x1 * cs[d] - x2 * sn[d];
        p[d + 64] = x2 * cs[d] + x1 * sn[d];
    }
}

// ======================= causal flash attention (tf32 MMA) =======================
// BM=BN=64, D=128, 256 threads. QK^T and PV on m16n8k8.tf32; S round-trips
// through smem so the validated smem softmax is reused unchanged.
#define AT_SMEM_FLOATS (3 * 64 * 132 + 64 * 68 + 3 * 64)
#define AT_SMEM_BYTES  (AT_SMEM_FLOATS * 4)

__global__ __launch_bounds__(256, 1)
void attn_kernel(const float* __restrict__ qkv, float* __restrict__ att)
{
    extern __shared__ float sm[];
    float (*q_s)[132] = (float (*)[132])(sm);
    float (*k_s)[132] = (float (*)[132])(sm + 64 * 132);
    float (*v_s)[132] = (float (*)[132])(sm + 2 * 64 * 132);
    float (*s_s)[68]  = (float (*)[68]) (sm + 3 * 64 * 132);
    float* m_s  = sm + 3 * 64 * 132 + 64 * 68;
    float* l_s  = m_s + 64;
    float* al_s = l_s + 64;

    const int qt = blockIdx.x;
    const int bh = blockIdx.y;
    const int b = bh >> 4, h = bh & 15, gq = h >> 2;
    const int tid  = threadIdx.x;
    const int warp = tid >> 5, lane = tid & 31;
    const int wm = warp >> 1;        // 0..3: 16 q-rows each
    const int wn = warp & 1;         // 0..1
    const int g  = lane >> 2;        // 0..7
    const int t  = lane & 3;         // 0..3
    const float scale = 0.088388347648318447f;   // 1/sqrt(128)

    const float* qb = qkv + (size_t)b * SS * QKV_LD + h * HD;
    const float* kb = qkv + (size_t)b * SS * QKV_LD + 2048 + gq * HD;
    const float* vb = qkv + (size_t)b * SS * QKV_LD + 2560 + gq * HD;

    // Load Q tile (64 x 128), tf32-converted
    {
        int c4 = tid & 31, r0 = tid >> 5;
#pragma unroll
        for (int i = 0; i < 8; i++) {
            int r = r0 + i * 8;
            float4 v = *(const float4*)(qb + (size_t)(qt * 64 + r) * QKV_LD + c4 * 4);
            float4 w;
            w.x = __uint_as_float(f2tf32(v.x));
            w.y = __uint_as_float(f2tf32(v.y));
            w.z = __uint_as_float(f2tf32(v.z));
            w.w = __uint_as_float(f2tf32(v.w));
            *(float4*)&q_s[r][c4 * 4] = w;
        }
    }
    if (tid < 64) { m_s[tid] = -1e30f; l_s[tid] = 0.0f; }

    // O accumulators: warp (wm,wn) owns rows wm*16+{g,g+8}, d-cols wn*64 + 8 tiles
    float oacc[8][4];
#pragma unroll
    for (int i = 0; i < 8; i++)
#pragma unroll
        for (int c = 0; c < 4; c++) oacc[i][c] = 0.0f;

    for (int jt = 0; jt <= qt; jt++) {
        // Load K,V tiles (tf32)
        {
            int c4 = tid & 31, r0 = tid >> 5;
#pragma unroll
            for (int i = 0; i < 8; i++) {
                int r = r0 + i * 8;
                size_t off = (size_t)(jt * 64 + r) * QKV_LD + c4 * 4;
                float4 kv4 = *(const float4*)(kb + off);
                float4 vv4 = *(const float4*)(vb + off);
                float4 wk4, wv4;
                wk4.x = __uint_as_float(f2tf32(kv4.x));
                wk4.y = __uint_as_float(f2tf32(kv4.y));
                wk4.z = __uint_as_float(f2tf32(kv4.z));
                wk4.w = __uint_as_float(f2tf32(kv4.w));
                wv4.x = __uint_as_float(f2tf32(vv4.x));
                wv4.y = __uint_as_float(f2tf32(vv4.y));
                wv4.z = __uint_as_float(f2tf32(vv4.z));
                wv4.w = __uint_as_float(f2tf32(vv4.w));
                *(float4*)&k_s[r][c4 * 4] = wk4;
                *(float4*)&v_s[r][c4 * 4] = wv4;
            }
        }
        __syncthreads();

        // S = Q K^T via MMA. Warp: m-tile rows wm*16, n-tiles wn*32 + 4 tiles.
        float sacc[4][4];
#pragma unroll
        for (int j = 0; j < 4; j++)
#pragma unroll
            for (int c = 0; c < 4; c++) sacc[j][c] = 0.0f;

#pragma unroll
        for (int kk = 0; kk < 16; kk++) {
            const int kb8 = kk * 8;
            uint32_t a0 = __float_as_uint(q_s[wm * 16 + g    ][kb8 + t    ]);
            uint32_t a1 = __float_as_uint(q_s[wm * 16 + g + 8][kb8 + t    ]);
            uint32_t a2 = __float_as_uint(q_s[wm * 16 + g    ][kb8 + t + 4]);
            uint32_t a3 = __float_as_uint(q_s[wm * 16 + g + 8][kb8 + t + 4]);
#pragma unroll
            for (int nt = 0; nt < 4; nt++) {
                int kr = wn * 32 + nt * 8 + g;   // K row (= S col group)
                uint32_t b0 = __float_as_uint(k_s[kr][kb8 + t    ]);
                uint32_t b1 = __float_as_uint(k_s[kr][kb8 + t + 4]);
                mma_tf32(sacc[nt], a0, a1, a2, a3, b0, b1);
            }
        }

        // Scale + causal mask + store fragments to s_s
        {
            int r0 = wm * 16 + g, r1 = r0 + 8;
            int gr0 = qt * 64 + r0, gr1 = qt * 64 + r1;
#pragma unroll
            for (int nt = 0; nt < 4; nt++) {
                int c0 = wn * 32 + nt * 8 + 2 * t;
                int gc0 = jt * 64 + c0;
                s_s[r0][c0]     = (gc0     > gr0) ? -1e30f : sacc[nt][0] * scale;
                s_s[r0][c0 + 1] = (gc0 + 1 > gr0) ? -1e30f : sacc[nt][1] * scale;
                s_s[r1][c0]     = (gc0     > gr1) ? -1e30f : sacc[nt][2] * scale;
                s_s[r1][c0 + 1] = (gc0 + 1 > gr1) ? -1e30f : sacc[nt][3] * scale;
            }
        }
        __syncthreads();

        // Online softmax on s_s (validated path; p stored tf32-converted)
#pragma unroll
        for (int rr = 0; rr < 8; rr++) {
            int r = warp * 8 + rr;
            float s0 = s_s[r][lane], s1 = s_s[r][lane + 32];
            float mt = fmaxf(s0, s1);
#pragma unroll
            for (int off = 16; off > 0; off >>= 1)
                mt = fmaxf(mt, __shfl_xor_sync(0xffffffffu, mt, off));
            float m_old = m_s[r];
            float m_new = fmaxf(m_old, mt);
            float p0 = __expf(s0 - m_new);
            float p1 = __expf(s1 - m_new);
            float ps = p0 + p1;
#pragma unroll
            for (int off = 16; off > 0; off >>= 1)
                ps += __shfl_xor_sync(0xffffffffu, ps, off);
            s_s[r][lane]      = __uint_as_float(f2tf32(p0));
            s_s[r][lane + 32] = __uint_as_float(f2tf32(p1));
            if (lane == 0) {
                float alpha = __expf(m_old - m_new);
                m_s[r]  = m_new;
                l_s[r]  = l_s[r] * alpha + ps;
                al_s[r] = alpha;
            }
        }
        __syncthreads();

        // Rescale O by alpha, then O += P V via MMA
        {
            float a_lo = al_s[wm * 16 + g];
            float a_hi = al_s[wm * 16 + g + 8];
#pragma unroll
            for (int nt = 0; nt < 8; nt++) {
                oacc[nt][0] *= a_lo;  oacc[nt][1] *= a_lo;
                oacc[nt][2] *= a_hi;  oacc[nt][3] *= a_hi;
            }
        }
#pragma unroll
        for (int kk = 0; kk < 8; kk++) {
            const int kb8 = kk * 8;
            uint32_t a0 = __float_as_uint(s_s[wm * 16 + g    ][kb8 + t    ]);
            uint32_t a1 = __float_as_uint(s_s[wm * 16 + g + 8][kb8 + t    ]);
            uint32_t a2 = __float_as_uint(s_s[wm * 16 + g    ][kb8 + t + 4]);
            uint32_t a3 = __float_as_uint(s_s[wm * 16 + g + 8][kb8 + t + 4]);
#pragma unroll
            for (int nt = 0; nt < 8; nt++) {
                int cn = wn * 64 + nt * 8 + g;
                uint32_t b0 = __float_as_uint(v_s[kb8 + t    ][cn]);
                uint32_t b1 = __float_as_uint(v_s[kb8 + t + 4][cn]);
                mma_tf32(oacc[nt], a0, a1, a2, a3, b0, b1);
            }
        }
        __syncthreads();
    }

    // Normalize and write O: rows wm*16+{g,g+8}, cols wn*64 + nt*8 + 2t
    {
        int r0 = wm * 16 + g, r1 = r0 + 8;
        float il0 = 1.0f / l_s[r0];
        float il1 = 1.0f / l_s[r1];
        size_t row0 = (size_t)(b * SS + qt * 64 + r0);
        size_t row1 = (size_t)(b * SS + qt * 64 + r1);
#pragma unroll
        for (int nt = 0; nt < 8; nt++) {
            int col = h * HD + wn * 64 + nt * 8 + 2 * t;
            float2 o0, o1;
            o0.x = oacc[nt][0] * il0;  o0.y = oacc[nt][1] * il0;
            o1.x = oacc[nt][2] * il1;  o1.y = oacc[nt][3] * il1;
            *(float2*)&att[row0 * HHID + col] = o0;
            *(float2*)&att[row1 * HHID + col] = o1;
        }
    }
}

// ======================= launch =======================
extern "C" void kernel_launch(void* const* d_in, const int* in_sizes, int n_in,
                              void* d_out, int out_size)
{
    const float* hidden = (const float*)d_in[0];
    const float* timev  = (const float*)d_in[1];
    const float* wq = (const float*)d_in[2];
    const float* bq = (const float*)d_in[3];
    const float* wk = (const float*)d_in[4];
    const float* bk = (const float*)d_in[5];
    const float* wv = (const float*)d_in[6];
    const float* bv = (const float*)d_in[7];
    const float* wo = (const float*)d_in[8];
    const float* rw = (const float*)d_in[9];
    float* out = (float*)d_out;

    float *qkv, *att, *zb;
    cudaGetSymbolAddress((void**)&qkv, g_qkv);
    cudaGetSymbolAddress((void**)&att, g_att);
    cudaGetSymbolAddress((void**)&zb,  g_zeros);

    cudaFuncSetAttribute(gemm_tf32_kernel, cudaFuncAttributeMaxDynamicSharedMemorySize, GM_SMEM_BYTES);
    cudaFuncSetAttribute(attn_kernel, cudaFuncAttributeMaxDynamicSharedMemorySize, AT_SMEM_BYTES);

    dim3 blk(256);
    // QKV projections -> [4096, 3072] scratch (q | k | v), tf32 tensor cores, cp.async pipelined
    gemm_tf32_kernel<<<dim3(16, 32), blk, GM_SMEM_BYTES>>>(hidden, wq, bq, qkv,        2048, 2048, QKV_LD);
    gemm_tf32_kernel<<<dim3(4, 32),  blk, GM_SMEM_BYTES>>>(hidden, wk, bk, qkv + 2048,  512, 2048, QKV_LD);
    gemm_tf32_kernel<<<dim3(4, 32),  blk, GM_SMEM_BYTES>>>(hidden, wv, bv, qkv + 2560,  512, 2048, QKV_LD);

    // Continuous-time RoPE on q and k (in place)
    rope_kernel<<<NTOK, 256>>>(qkv, timev, rw);

    // Causal GQA flash attention (tf32 MMA) -> [4096, 2048]
    attn_kernel<<<dim3(SS / 64, BB * NH), blk, AT_SMEM_BYTES>>>(qkv, att);

    // Output projection -> d_out [4096, 2048], tf32 tensor cores, cp.async pipelined
    gemm_tf32_kernel<<<dim3(16, 32), blk, GM_SMEM_BYTES>>>(att, wo, zb, out, 2048, 2048, 2048);
}